// round 8
// baseline (speedup 1.0000x reference)
#include <cuda_runtime.h>
#include <cstdint>

#define BATCH 256
#define QNUM 900
#define CNUM 91
#define QC (QNUM * CNUM)        // 81900
#define NVR (QC / 4)            // 20475 float4 per row
#define K_SEL 100
#define CAPC 1024
#define THR 2.75f
#define SEGS 8
#define SEG_F4 2560             // 8*2560 >= 20475
#define T 256
#define F4PT 10                 // 2560/256
#define SBUF_CAP 512

__device__ int g_cnt[BATCH];                         // zero-init; reset by row winner
__device__ int g_done[BATCH];                        // zero-init; reset by row winner
__device__ unsigned long long g_cand[BATCH * CAPC];  // 2 MB scratch

__device__ __forceinline__ uint32_t mono(float f) {
    uint32_t u = __float_as_uint(f);
    return u ^ ((u >> 31) ? 0xFFFFFFFFu : 0x80000000u);
}
__device__ __forceinline__ float unmono(uint32_t m) {
    uint32_t u = (m & 0x80000000u) ? (m ^ 0x80000000u) : ~m;
    return __uint_as_float(u);
}

__global__ __launch_bounds__(T)
void fused_kernel(const float* __restrict__ logits,
                  const float* __restrict__ boxes_in,
                  const float* __restrict__ tsizes,
                  float* __restrict__ out)
{
    // cand doubles as the scan staging buffer (first SBUF_CAP slots)
    __shared__ unsigned long long cand[CAPC + 8];
    __shared__ unsigned long long topk[K_SEL];
    __shared__ int hist[256];
    __shared__ int scnt, sbase, scopy, s_last, s_cnt2, s_digit, s_greater;
    __shared__ float bx0[K_SEL], by0[K_SEL], bx1[K_SEL], by1[K_SEL];
    __shared__ float barea[K_SEL], sscore[K_SEL];
    __shared__ uint4 sup4[K_SEL + 1];
    __shared__ uint32_t keepw[4];

    const int c = blockIdx.x;
    const int b = c >> 3;        // row
    const int s = c & 7;         // segment
    const int tid = threadIdx.x;
    const float4* row = (const float4*)(logits + (size_t)b * QC);

    // ---------------- scan phase: smem staging ----------------
    if (tid == 0) scnt = 0;
    __syncthreads();

    {
        const int base = s * SEG_F4 + tid;
        #pragma unroll
        for (int k = 0; k < F4PT; k++) {
            int i = base + k * T;
            if (i < NVR) {
                float4 v = row[i];
                float vmax = fmaxf(fmaxf(v.x, v.y), fmaxf(v.z, v.w));
                if (vmax > THR) {
                    float vl[4] = {v.x, v.y, v.z, v.w};
                    #pragma unroll
                    for (int l = 0; l < 4; l++) {
                        if (vl[l] > THR) {
                            int p = atomicAdd(&scnt, 1);
                            if (p < SBUF_CAP) {
                                uint32_t idx = (uint32_t)(i * 4 + l);
                                cand[p] = ((unsigned long long)mono(vl[l]) << 32)
                                          | (0xFFFFFFFFu - idx);
                            }
                        }
                    }
                }
            }
        }
    }
    __syncthreads();

    if (tid == 0) {
        int cnt = scnt;
        int stored = min(cnt, SBUF_CAP);
        int add = (cnt > SBUF_CAP) ? (CAPC + 1) : cnt;   // overflow -> force fallback
        sbase = atomicAdd(&g_cnt[b], add);
        scopy = stored;
    }
    __syncthreads();

    {
        int stored = scopy, gb = sbase;
        for (int i = tid; i < stored; i += T) {
            int p = gb + i;
            if (p < CAPC) g_cand[b * CAPC + p] = cand[i];
        }
    }

    // ---------------- ticket: 8th finisher of this row runs post inline ----------------
    __threadfence();
    __syncthreads();
    if (tid == 0)
        s_last = (atomicAdd(&g_done[b], 1) == SEGS - 1);
    __syncthreads();
    if (!s_last) return;
    __threadfence();   // acquire: order candidate reads after ticket observation

    int n = g_cnt[b];

    if (n >= K_SEL && n <= CAPC) {
        // fast path (L2-hot)
        for (int i = tid; i < n; i += T)
            cand[i] = g_cand[b * CAPC + i];
    } else {
        // ---- exact radix-select fallback (statistically never taken) ----
        uint32_t prefix = 0, pmask = 0;
        int need = K_SEL;
        for (int level = 3; level >= 0; level--) {
            for (int d = tid; d < 256; d += T) hist[d] = 0;
            __syncthreads();
            for (int i = tid; i < NVR; i += T) {
                float4 v = row[i];
                float vl[4] = {v.x, v.y, v.z, v.w};
                #pragma unroll
                for (int l = 0; l < 4; l++) {
                    uint32_t m = mono(vl[l]);
                    if ((m & pmask) == prefix)
                        atomicAdd(&hist[(m >> (8 * level)) & 255u], 1);
                }
            }
            __syncthreads();
            if (tid == 0) {
                int acc = 0, dsel = 0;
                for (int d = 255; d >= 0; d--) {
                    int h = hist[d];
                    if (acc + h >= need) { dsel = d; break; }
                    acc += h;
                }
                s_digit = dsel;
                s_greater = acc;
            }
            __syncthreads();
            need -= s_greater;
            prefix |= ((uint32_t)s_digit) << (8 * level);
            pmask  |= 0xFFu << (8 * level);
            __syncthreads();
        }
        if (tid == 0) s_cnt2 = 0;
        __syncthreads();
        for (int i = tid; i < NVR; i += T) {
            float4 v = row[i];
            float vl[4] = {v.x, v.y, v.z, v.w};
            #pragma unroll
            for (int l = 0; l < 4; l++) {
                uint32_t m = mono(vl[l]);
                if (m >= prefix) {
                    int p = atomicAdd(&s_cnt2, 1);
                    if (p < CAPC) {
                        uint32_t idx = (uint32_t)(i * 4 + l);
                        cand[p] = ((unsigned long long)m << 32) | (0xFFFFFFFFu - idx);
                    }
                }
            }
        }
        __syncthreads();
        n = min(s_cnt2, CAPC);
    }
    __syncthreads();
    if (tid < 8) cand[n + tid] = 0ULL;   // pad
    __syncthreads();

    // ---- rank-by-counting top-100, unroll-8 (keys unique) ----
    {
        int n8 = (n + 7) & ~7;
        for (int t = tid; t < n; t += T) {
            unsigned long long key = cand[t];
            int rank = 0;
            for (int j = 0; j < n8; j += 8) {
                rank += (int)(cand[j + 0] > key) + (int)(cand[j + 1] > key)
                      + (int)(cand[j + 2] > key) + (int)(cand[j + 3] > key)
                      + (int)(cand[j + 4] > key) + (int)(cand[j + 5] > key)
                      + (int)(cand[j + 6] > key) + (int)(cand[j + 7] > key);
            }
            if (rank < K_SEL) topk[rank] = key;
        }
    }
    __syncthreads();

    // ---- top-100 decode ----
    const int BK = BATCH * K_SEL;   // 25600
    if (tid < K_SEL) {
        unsigned long long e = topk[tid];
        uint32_t m = (uint32_t)(e >> 32);
        uint32_t idx = 0xFFFFFFFFu - (uint32_t)(e & 0xFFFFFFFFu);
        float logit = unmono(m);
        float score = 1.0f / (1.0f + expf(-logit));
        int q = idx / CNUM;
        int lab = idx - q * CNUM;
        const float* bp = boxes_in + ((size_t)b * QNUM + q) * 4;
        float cx = bp[0], cy = bp[1], w = bp[2], h = bp[3];
        float img_h = tsizes[2 * b], img_w = tsizes[2 * b + 1];
        float x0 = (cx - 0.5f * w) * img_w;
        float y0 = (cy - 0.5f * h) * img_h;
        float x1 = (cx + 0.5f * w) * img_w;
        float y1 = (cy + 0.5f * h) * img_h;
        bx0[tid] = x0; by0[tid] = y0; bx1[tid] = x1; by1[tid] = y1;
        barea[tid] = (x1 - x0) * (y1 - y0);
        sscore[tid] = score;

        int o = b * K_SEL + tid;
        out[o] = score;
        out[BK + o] = (float)lab;
        float* ob = out + 2 * BK + (size_t)o * 4;
        ob[0] = x0; ob[1] = y0; ob[2] = x1; ob[3] = y1;
    }
    __syncthreads();

    // ---- NMS suppression bitmask ----
    if (tid < K_SEL) {
        float x0i = bx0[tid], y0i = by0[tid], x1i = bx1[tid], y1i = by1[tid];
        float ai = barea[tid];
        uint32_t mm[4] = {0, 0, 0, 0};
        #pragma unroll 4
        for (int j = tid + 1; j < K_SEL; j++) {
            float lx = fmaxf(x0i, bx0[j]);
            float ly = fmaxf(y0i, by0[j]);
            float rx = fminf(x1i, bx1[j]);
            float ry = fminf(y1i, by1[j]);
            float iw = fmaxf(rx - lx, 0.0f);
            float ih = fmaxf(ry - ly, 0.0f);
            float inter = iw * ih;
            float uni = ai + barea[j] - inter;
            float iou = inter / fmaxf(uni, 1e-9f);
            if (iou > 0.7f)
                mm[j >> 5] |= 1u << (j & 31);
        }
        sup4[tid] = make_uint4(mm[0], mm[1], mm[2], mm[3]);
    }
    if (tid == 0) sup4[K_SEL] = make_uint4(0, 0, 0, 0);
    __syncthreads();

    // ---- serial greedy chain (prefetched) ----
    if (tid == 0) {
        uint32_t k0 = ~0u, k1 = ~0u, k2 = ~0u, k3 = ~0u;
        uint4 sv = sup4[0];
        #pragma unroll 1
        for (int i = 0; i < 32; i++) {
            uint4 sn = sup4[i + 1];
            if ((k0 >> i) & 1u) { k0 &= ~sv.x; k1 &= ~sv.y; k2 &= ~sv.z; k3 &= ~sv.w; }
            sv = sn;
        }
        #pragma unroll 1
        for (int i = 32; i < 64; i++) {
            uint4 sn = sup4[i + 1];
            if ((k1 >> (i - 32)) & 1u) { k0 &= ~sv.x; k1 &= ~sv.y; k2 &= ~sv.z; k3 &= ~sv.w; }
            sv = sn;
        }
        #pragma unroll 1
        for (int i = 64; i < 96; i++) {
            uint4 sn = sup4[i + 1];
            if ((k2 >> (i - 64)) & 1u) { k0 &= ~sv.x; k1 &= ~sv.y; k2 &= ~sv.z; k3 &= ~sv.w; }
            sv = sn;
        }
        #pragma unroll 1
        for (int i = 96; i < K_SEL; i++) {
            uint4 sn = sup4[i + 1];
            if ((k3 >> (i - 96)) & 1u) { k0 &= ~sv.x; k1 &= ~sv.y; k2 &= ~sv.z; k3 &= ~sv.w; }
            sv = sn;
        }
        keepw[0] = k0; keepw[1] = k1; keepw[2] = k2; keepw[3] = k3;
    }
    __syncthreads();
    if (tid < K_SEL) {
        int o = b * K_SEL + tid;
        bool kb = (keepw[tid >> 5] >> (tid & 31)) & 1u;
        out[6 * BK + o] = (sscore[tid] > 0.3f && kb) ? 1.0f : 0.0f;
    }

    // reset row state for next replay (sole owner of row b here)
    if (tid == 0) {
        g_cnt[b] = 0;
        g_done[b] = 0;
    }
}

extern "C" void kernel_launch(void* const* d_in, const int* in_sizes, int n_in,
                              void* d_out, int out_size)
{
    const float* logits   = (const float*)d_in[0];   // (256, 900, 91) f32
    const float* boxes_in = (const float*)d_in[1];   // (256, 900, 4)  f32
    const float* tsizes   = (const float*)d_in[2];   // (256, 2)       f32
    float* out = (float*)d_out;
    fused_kernel<<<BATCH * SEGS, T>>>(logits, boxes_in, tsizes, out);
}

// round 9
// speedup vs baseline: 1.1236x; 1.1236x over previous
#include <cuda_runtime.h>
#include <cstdint>

#define BATCH 256
#define QNUM 900
#define CNUM 91
#define QC (QNUM * CNUM)        // 81900
#define NVR (QC / 4)            // 20475 float4 per row
#define K_SEL 100
#define CAPC 1024
#define THR 2.75f
#define SEGS 8
#define SEG_F4 2560
#define T 256
#define F4PT 10
#define SBUF_CAP 512
#define WCAP 520                // per-warp key capacity (512 + pad)

// exact midpoint between 0.7f and nextafter(0.7f): RN(x) > 0.7f  <=>  x >= IOU_MID
#define IOU_MID 0.7000000178813934326171875

__device__ int g_cnt[BATCH];
__device__ unsigned long long g_cand[BATCH * CAPC];

__device__ __forceinline__ uint32_t mono(float f) {
    uint32_t u = __float_as_uint(f);
    return u ^ ((u >> 31) ? 0xFFFFFFFFu : 0x80000000u);
}
__device__ __forceinline__ float unmono(uint32_t m) {
    uint32_t u = (m & 0x80000000u) ? (m ^ 0x80000000u) : ~m;
    return __uint_as_float(u);
}

// ---------------- Phase 1: streaming scan, smem staging (proven ~12us @ ~7TB/s) ----------------
__global__ __launch_bounds__(T)
void scan_kernel(const float* __restrict__ logits)
{
    __shared__ unsigned long long sbuf[SBUF_CAP];
    __shared__ int scnt, sbase, scopy;

    const int c = blockIdx.x;
    const int b = c >> 3;
    const int s = c & 7;
    const int tid = threadIdx.x;
    const float4* row = (const float4*)(logits + (size_t)b * QC);

    if (tid == 0) scnt = 0;
    __syncthreads();

    const int base = s * SEG_F4 + tid;
    #pragma unroll
    for (int k = 0; k < F4PT; k++) {
        int i = base + k * T;
        if (i < NVR) {
            float4 v = row[i];
            float vmax = fmaxf(fmaxf(v.x, v.y), fmaxf(v.z, v.w));
            if (vmax > THR) {
                float vl[4] = {v.x, v.y, v.z, v.w};
                #pragma unroll
                for (int l = 0; l < 4; l++) {
                    if (vl[l] > THR) {
                        int p = atomicAdd(&scnt, 1);
                        if (p < SBUF_CAP) {
                            uint32_t idx = (uint32_t)(i * 4 + l);
                            sbuf[p] = ((unsigned long long)mono(vl[l]) << 32)
                                      | (0xFFFFFFFFu - idx);
                        }
                    }
                }
            }
        }
    }
    __syncthreads();

    if (tid == 0) {
        int cnt = scnt;
        int stored = min(cnt, SBUF_CAP);
        int add = (cnt > SBUF_CAP) ? (CAPC + 1) : cnt;   // overflow -> force fallback
        sbase = atomicAdd(&g_cnt[b], add);
        scopy = stored;
    }
    __syncthreads();

    int stored = scopy, gb = sbase;
    for (int i = tid; i < stored; i += T) {
        int p = gb + i;
        if (p < CAPC) g_cand[b * CAPC + p] = sbuf[i];
    }
}

// ---------------- Phase 2: ONE WARP PER ROW, zero block barriers ----------------
__global__ __launch_bounds__(64)
void post_kernel(const float* __restrict__ logits,
                 const float* __restrict__ boxes_in,
                 const float* __restrict__ tsizes,
                 float* __restrict__ out)
{
    __shared__ unsigned long long skey[2][WCAP];
    __shared__ unsigned long long stopk[2][K_SEL];
    __shared__ float sx0[2][K_SEL], sy0[2][K_SEL], sx1[2][K_SEL], sy1[2][K_SEL];
    __shared__ float sar[2][K_SEL], ssc[2][K_SEL];
    __shared__ uint4 ssup[2][K_SEL];
    __shared__ int sfcnt[2];
    __shared__ uint32_t skeep[2][4];

    const int w = threadIdx.x >> 5;
    const int lane = threadIdx.x & 31;
    const int row = blockIdx.x * 2 + w;
    const float4* rp = (const float4*)(logits + (size_t)row * QC);

    int n = g_cnt[row];

    if (n >= K_SEL && n <= 512) {
        for (int i = lane; i < n; i += 32)
            skey[w][i] = g_cand[row * CAPC + i];
    } else {
        // ---- exact warp-level fallback: bit-descend max threshold with count >= K ----
        uint32_t t = 0;
        for (int bit = 31; bit >= 0; bit--) {
            uint32_t t2 = t | (1u << bit);
            int c = 0;
            for (int i = lane; i < NVR; i += 32) {
                float4 v = rp[i];
                c += (int)(mono(v.x) >= t2) + (int)(mono(v.y) >= t2)
                   + (int)(mono(v.z) >= t2) + (int)(mono(v.w) >= t2);
            }
            c = __reduce_add_sync(0xFFFFFFFFu, c);
            if (c >= K_SEL) t = t2;
        }
        if (lane == 0) sfcnt[w] = 0;
        __syncwarp();
        for (int i = lane; i < NVR; i += 32) {
            float4 v = rp[i];
            float vl[4] = {v.x, v.y, v.z, v.w};
            #pragma unroll
            for (int l = 0; l < 4; l++) {
                uint32_t m = mono(vl[l]);
                if (m >= t) {
                    int p = atomicAdd(&sfcnt[w], 1);
                    if (p < WCAP - 8) {
                        uint32_t idx = (uint32_t)(i * 4 + l);
                        skey[w][p] = ((unsigned long long)m << 32) | (0xFFFFFFFFu - idx);
                    }
                }
            }
        }
        __syncwarp();
        n = min(sfcnt[w], WCAP - 8);
    }
    __syncwarp();
    if (lane < 8) skey[w][n + lane] = 0ULL;   // pad (0 < any real key)
    __syncwarp();

    // ---- rank-by-counting, FLIPPED: 8 keys/lane in regs, one pass over skey ----
    const int n4 = (n + 3) & ~3;
    {
        unsigned long long myk[8];
        int myr[8];
        #pragma unroll
        for (int r = 0; r < 8; r++) {
            int tt = lane + 32 * r;
            myk[r] = (tt < n) ? skey[w][tt] : 0ULL;
            myr[r] = 0;
        }
        for (int j = 0; j < n4; j += 4) {
            unsigned long long a = skey[w][j + 0];
            unsigned long long b2 = skey[w][j + 1];
            unsigned long long c2 = skey[w][j + 2];
            unsigned long long d = skey[w][j + 3];
            #pragma unroll
            for (int r = 0; r < 8; r++)
                myr[r] += (int)(a > myk[r]) + (int)(b2 > myk[r])
                        + (int)(c2 > myk[r]) + (int)(d > myk[r]);
        }
        #pragma unroll
        for (int r = 0; r < 8; r++) {
            int tt = lane + 32 * r;
            if (tt < n && myr[r] < K_SEL) stopk[w][myr[r]] = myk[r];
        }
    }
    if (n > 256) {   // second key block (keys 256..511), ~22% of rows
        unsigned long long myk[8];
        int myr[8];
        #pragma unroll
        for (int r = 0; r < 8; r++) {
            int tt = 256 + lane + 32 * r;
            myk[r] = (tt < n) ? skey[w][tt] : 0ULL;
            myr[r] = 0;
        }
        for (int j = 0; j < n4; j += 4) {
            unsigned long long a = skey[w][j + 0];
            unsigned long long b2 = skey[w][j + 1];
            unsigned long long c2 = skey[w][j + 2];
            unsigned long long d = skey[w][j + 3];
            #pragma unroll
            for (int r = 0; r < 8; r++)
                myr[r] += (int)(a > myk[r]) + (int)(b2 > myk[r])
                        + (int)(c2 > myk[r]) + (int)(d > myk[r]);
        }
        #pragma unroll
        for (int r = 0; r < 8; r++) {
            int tt = 256 + lane + 32 * r;
            if (tt < n && myr[r] < K_SEL) stopk[w][myr[r]] = myk[r];
        }
    }
    __syncwarp();

    // ---- top-100 decode (entries e = lane, lane+32, lane+64, lane+96) ----
    const int BK = BATCH * K_SEL;
    const float img_h = tsizes[2 * row], img_w = tsizes[2 * row + 1];
    for (int e = lane; e < K_SEL; e += 32) {
        unsigned long long k = stopk[w][e];
        uint32_t m = (uint32_t)(k >> 32);
        uint32_t idx = 0xFFFFFFFFu - (uint32_t)(k & 0xFFFFFFFFu);
        float logit = unmono(m);
        float score = 1.0f / (1.0f + expf(-logit));
        int q = idx / CNUM;
        int lab = idx - q * CNUM;
        float4 bx = *(const float4*)(boxes_in + ((size_t)row * QNUM + q) * 4);
        float x0 = (bx.x - 0.5f * bx.z) * img_w;
        float y0 = (bx.y - 0.5f * bx.w) * img_h;
        float x1 = (bx.x + 0.5f * bx.z) * img_w;
        float y1 = (bx.y + 0.5f * bx.w) * img_h;
        sx0[w][e] = x0; sy0[w][e] = y0; sx1[w][e] = x1; sy1[w][e] = y1;
        sar[w][e] = (x1 - x0) * (y1 - y0);
        ssc[w][e] = score;

        int o = row * K_SEL + e;
        out[o] = score;
        out[BK + o] = (float)lab;
        float* ob = out + 2 * BK + (size_t)o * 4;
        ob[0] = x0; ob[1] = y0; ob[2] = x1; ob[3] = y1;
    }
    __syncwarp();

    // ---- NMS masks, flipped: 4 i's per lane in regs, j outer, div-free exact test ----
    {
        float ix0[4], iy0[4], ix1[4], iy1[4], iar[4];
        uint32_t msk[4][4];
        #pragma unroll
        for (int r = 0; r < 4; r++) {
            int i = lane + 32 * r;
            bool va = (i < K_SEL);
            ix0[r] = va ? sx0[w][i] : 0.0f;
            iy0[r] = va ? sy0[w][i] : 0.0f;
            ix1[r] = va ? sx1[w][i] : 0.0f;
            iy1[r] = va ? sy1[w][i] : 0.0f;
            iar[r] = va ? sar[w][i] : 0.0f;
            #pragma unroll
            for (int q2 = 0; q2 < 4; q2++) msk[r][q2] = 0;
        }
        #pragma unroll
        for (int jw = 0; jw < 4; jw++) {
            const int jend = (jw == 3) ? 4 : 32;
            for (int jb = 0; jb < jend; jb++) {
                int j = jw * 32 + jb;
                float jx0 = sx0[w][j], jy0 = sy0[w][j];
                float jx1 = sx1[w][j], jy1 = sy1[w][j];
                float jar = sar[w][j];
                #pragma unroll
                for (int r = 0; r < 4; r++) {
                    int i = lane + 32 * r;
                    float lx = fmaxf(ix0[r], jx0);
                    float ly = fmaxf(iy0[r], jy0);
                    float rx = fminf(ix1[r], jx1);
                    float ry = fminf(iy1[r], jy1);
                    float iw = fmaxf(rx - lx, 0.0f);
                    float ih = fmaxf(ry - ly, 0.0f);
                    float inter = iw * ih;
                    float uni = fmaxf(iar[r] + jar - inter, 1e-9f);
                    // exact: RN(inter/uni) > 0.7f  <=>  inter >= IOU_MID * uni (real arith)
                    bool sup = ((double)inter >= IOU_MID * (double)uni);
                    if (sup && j > i)
                        msk[r][jw] |= 1u << jb;
                }
            }
        }
        #pragma unroll
        for (int r = 0; r < 4; r++) {
            int i = lane + 32 * r;
            if (i < K_SEL)
                ssup[w][i] = make_uint4(msk[r][0], msk[r][1], msk[r][2], msk[r][3]);
        }
    }
    __syncwarp();

    // ---- serial greedy chain (lane 0; hidden by sibling warp) ----
    if (lane == 0) {
        uint32_t k0 = ~0u, k1 = ~0u, k2 = ~0u, k3 = ~0u;
        #pragma unroll 1
        for (int i = 0; i < 32; i++) {
            if ((k0 >> i) & 1u) { uint4 s = ssup[w][i]; k0 &= ~s.x; k1 &= ~s.y; k2 &= ~s.z; k3 &= ~s.w; }
        }
        #pragma unroll 1
        for (int i = 32; i < 64; i++) {
            if ((k1 >> (i - 32)) & 1u) { uint4 s = ssup[w][i]; k0 &= ~s.x; k1 &= ~s.y; k2 &= ~s.z; k3 &= ~s.w; }
        }
        #pragma unroll 1
        for (int i = 64; i < 96; i++) {
            if ((k2 >> (i - 64)) & 1u) { uint4 s = ssup[w][i]; k0 &= ~s.x; k1 &= ~s.y; k2 &= ~s.z; k3 &= ~s.w; }
        }
        #pragma unroll 1
        for (int i = 96; i < K_SEL; i++) {
            if ((k3 >> (i - 96)) & 1u) { uint4 s = ssup[w][i]; k0 &= ~s.x; k1 &= ~s.y; k2 &= ~s.z; k3 &= ~s.w; }
        }
        skeep[w][0] = k0; skeep[w][1] = k1; skeep[w][2] = k2; skeep[w][3] = k3;
    }
    __syncwarp();

    for (int e = lane; e < K_SEL; e += 32) {
        int o = row * K_SEL + e;
        bool kb = (skeep[w][e >> 5] >> (e & 31)) & 1u;
        out[6 * BK + o] = (ssc[w][e] > 0.3f && kb) ? 1.0f : 0.0f;
    }

    if (lane == 0) g_cnt[row] = 0;   // reset for next replay
}

extern "C" void kernel_launch(void* const* d_in, const int* in_sizes, int n_in,
                              void* d_out, int out_size)
{
    const float* logits   = (const float*)d_in[0];   // (256, 900, 91) f32
    const float* boxes_in = (const float*)d_in[1];   // (256, 900, 4)  f32
    const float* tsizes   = (const float*)d_in[2];   // (256, 2)       f32
    float* out = (float*)d_out;
    scan_kernel<<<BATCH * SEGS, T>>>(logits);
    post_kernel<<<BATCH / 2, 64>>>(logits, boxes_in, tsizes, out);
}